// round 12
// baseline (speedup 1.0000x reference)
#include <cuda_runtime.h>
#include <cuda_fp16.h>
#include <math.h>
#include <stdint.h>

// Problem dims
#define V_ 32000
#define E_ 1024
#define H_ 1024
#define A_ 10
#define S_ 512
#define B_ 64

#define NSPA 32                // attention S-splits (16 rows each)
#define NTILES (V_ / 128)      // 250 logits n-tiles

// Scratch layout (floats)
#define OFF_HWA1 0             // 640
#define OFF_XCH  1024          // 64*2048 fp16 = 65536 floats
#define OFF_HLH  66560         // 64*1024 fp16 = 32768 floats
#define OFF_GIP  99328         // 8*B*3H = 1572864
#define OFF_GHP  1672192       // 4*B*3H = 786432
#define OFF_CP   2458624       // NSPA*B*H = 2097152
#define OFF_ML   4555776       // NSPA*B*2 = 4096
#define OFF_AH   4559872       // B*H fp16 = 32768 floats
#define SCRATCH_FLOATS 4592640

__device__ float g_scratch[SCRATCH_FLOATS];
__device__ int g_tile_ctr = 0;     // logits work-stealing counter

// ---------------------------------------------------------------------------
// hWa1[b][a] = sum_h h_last[b,h]*Wa1[a,h]; also emit h_last as fp16
// ---------------------------------------------------------------------------
__global__ __launch_bounds__(256) void k_hWa1(const float* __restrict__ h,
                                              const float* __restrict__ Wa1,
                                              float* __restrict__ hWa1,
                                              __half* __restrict__ hlh)
{
    const int b = blockIdx.x;
    const int tid = threadIdx.x;
    float4 hv = ((const float4*)(h + (size_t)b * H_))[tid];
    {
        __half2 p0 = __floats2half2_rn(hv.x, hv.y);
        __half2 p1 = __floats2half2_rn(hv.z, hv.w);
        uint2 pk;
        pk.x = *reinterpret_cast<uint32_t*>(&p0);
        pk.y = *reinterpret_cast<uint32_t*>(&p1);
        *(uint2*)(hlh + (size_t)b * H_ + 4 * tid) = pk;
    }
    float p[A_];
#pragma unroll
    for (int a = 0; a < A_; a++) {
        float4 w = ((const float4*)(Wa1 + (size_t)a * (2 * H_)))[tid];
        p[a] = hv.x * w.x + hv.y * w.y + hv.z * w.z + hv.w * w.w;
    }
    __shared__ float red[8][A_];
    const int lane = tid & 31, wid = tid >> 5;
#pragma unroll
    for (int a = 0; a < A_; a++) {
        float v = p[a];
        v += __shfl_xor_sync(0xffffffffu, v, 16);
        v += __shfl_xor_sync(0xffffffffu, v, 8);
        v += __shfl_xor_sync(0xffffffffu, v, 4);
        v += __shfl_xor_sync(0xffffffffu, v, 2);
        v += __shfl_xor_sync(0xffffffffu, v, 1);
        if (lane == 0) red[wid][a] = v;
    }
    __syncthreads();
    if (tid < A_) {
        float s = 0.f;
#pragma unroll
        for (int w = 0; w < 8; w++) s += red[w][tid];
        hWa1[b * A_ + tid] = s;
    }
}

// ---------------------------------------------------------------------------
// fused attention: one enc pass. Block = (b, 16-row s-chunk).
// Phase 1: stage enc rows to smem. Phase 2: warps 0-3 score 4 rows each.
// Phase 3: all threads build local softmax numerator context + (m, l).
// ---------------------------------------------------------------------------
#define ATT_SMEM_FLOATS (A_ * H_ + 16 * H_ + 16 + A_ + A_ + 12)

__global__ __launch_bounds__(256) void k_attn(const float* __restrict__ enc,
                                              const float* __restrict__ Wa1,
                                              const float* __restrict__ Wa2,
                                              const float* __restrict__ hWa1,
                                              float* __restrict__ cp,
                                              float* __restrict__ ml)
{
    extern __shared__ float sm[];
    float* Wsh = sm;                   // A_*H_
    float* encS = sm + A_ * H_;        // 16*H_
    float* esm = encS + 16 * H_;       // 16
    float* hWs = esm + 16;             // A_
    float* wa2s = hWs + A_;            // A_

    const int b = blockIdx.x, sp = blockIdx.y;
    const int tid = threadIdx.x, wid = tid >> 5, lane = tid & 31;
    const int s0 = sp * 16;

    // Wa1 second half -> smem
    for (int id = tid; id < A_ * (H_ / 4); id += 256) {
        int a = id >> 8, c4 = id & 255;
        ((float4*)Wsh)[a * 256 + c4] =
            *(const float4*)(Wa1 + (size_t)a * (2 * H_) + H_ + (c4 << 2));
    }
    if (tid < A_) { hWs[tid] = hWa1[b * A_ + tid]; wa2s[tid] = Wa2[tid]; }

    // stage 16 enc rows: 16 threads per row, 16 float4 each (coalesced)
    {
        const int r = tid >> 4, t16 = tid & 15;
        const float4* src = (const float4*)(enc + ((size_t)(s0 + r) * B_ + b) * H_);
        float4* dst = (float4*)(encS + r * H_);
#pragma unroll
        for (int q = 0; q < 16; q++) dst[t16 + 16 * q] = src[t16 + 16 * q];
    }
    __syncthreads();

    // score phase: warp w handles rows 4w..4w+3
    if (wid < 4) {
        float acc0[A_], acc1[A_], acc2[A_], acc3[A_];
#pragma unroll
        for (int a = 0; a < A_; a++) { acc0[a] = 0.f; acc1[a] = 0.f; acc2[a] = 0.f; acc3[a] = 0.f; }
        const float4* r0p = (const float4*)(encS + (wid * 4 + 0) * H_);
        const float4* r1p = (const float4*)(encS + (wid * 4 + 1) * H_);
        const float4* r2p = (const float4*)(encS + (wid * 4 + 2) * H_);
        const float4* r3p = (const float4*)(encS + (wid * 4 + 3) * H_);
#pragma unroll
        for (int q = 0; q < 8; q++) {
            const int i4 = lane + 32 * q;
            float4 x0 = r0p[i4];
            float4 x1 = r1p[i4];
            float4 x2 = r2p[i4];
            float4 x3 = r3p[i4];
#pragma unroll
            for (int a = 0; a < A_; a++) {
                float4 w = ((const float4*)(Wsh + a * H_))[i4];
                acc0[a] += x0.x * w.x + x0.y * w.y + x0.z * w.z + x0.w * w.w;
                acc1[a] += x1.x * w.x + x1.y * w.y + x1.z * w.z + x1.w * w.w;
                acc2[a] += x2.x * w.x + x2.y * w.y + x2.z * w.z + x2.w * w.w;
                acc3[a] += x3.x * w.x + x3.y * w.y + x3.z * w.z + x3.w * w.w;
            }
        }
#pragma unroll
        for (int a = 0; a < A_; a++) {
            float v;
            v = acc0[a];
            v += __shfl_xor_sync(0xffffffffu, v, 16); v += __shfl_xor_sync(0xffffffffu, v, 8);
            v += __shfl_xor_sync(0xffffffffu, v, 4);  v += __shfl_xor_sync(0xffffffffu, v, 2);
            v += __shfl_xor_sync(0xffffffffu, v, 1);  acc0[a] = v;
            v = acc1[a];
            v += __shfl_xor_sync(0xffffffffu, v, 16); v += __shfl_xor_sync(0xffffffffu, v, 8);
            v += __shfl_xor_sync(0xffffffffu, v, 4);  v += __shfl_xor_sync(0xffffffffu, v, 2);
            v += __shfl_xor_sync(0xffffffffu, v, 1);  acc1[a] = v;
            v = acc2[a];
            v += __shfl_xor_sync(0xffffffffu, v, 16); v += __shfl_xor_sync(0xffffffffu, v, 8);
            v += __shfl_xor_sync(0xffffffffu, v, 4);  v += __shfl_xor_sync(0xffffffffu, v, 2);
            v += __shfl_xor_sync(0xffffffffu, v, 1);  acc2[a] = v;
            v = acc3[a];
            v += __shfl_xor_sync(0xffffffffu, v, 16); v += __shfl_xor_sync(0xffffffffu, v, 8);
            v += __shfl_xor_sync(0xffffffffu, v, 4);  v += __shfl_xor_sync(0xffffffffu, v, 2);
            v += __shfl_xor_sync(0xffffffffu, v, 1);  acc3[a] = v;
        }
        float tsum[A_];
#pragma unroll
        for (int a = 0; a < A_; a++) {
            float t = acc0[a];
            if (lane == 1) t = acc1[a];
            if (lane == 2) t = acc2[a];
            if (lane == 3) t = acc3[a];
            tsum[a] = t;
        }
        if (lane < 4) {
            float ev = 0.f;
#pragma unroll
            for (int a = 0; a < A_; a++)
                ev += wa2s[a] * tanhf(hWs[a] + tsum[a]);
            esm[wid * 4 + lane] = ev;
        }
    }
    __syncthreads();

    // local softmax numerator context: thread owns float4 h-slot tid
    float mx = esm[0];
#pragma unroll
    for (int r = 1; r < 16; r++) mx = fmaxf(mx, esm[r]);
    float l = 0.f;
    float4 c4 = make_float4(0.f, 0.f, 0.f, 0.f);
#pragma unroll
    for (int r = 0; r < 16; r++) {
        const float wr = expf(esm[r] - mx);
        l += wr;
        float4 v = ((const float4*)(encS + r * H_))[tid];
        c4.x += wr * v.x; c4.y += wr * v.y; c4.z += wr * v.z; c4.w += wr * v.w;
    }
    ((float4*)(cp + ((size_t)sp * B_ + b) * H_))[tid] = c4;
    if (tid == 0) {
        ml[(sp * B_ + b) * 2] = mx;
        ml[(sp * B_ + b) * 2 + 1] = l;
    }
}

// ---------------------------------------------------------------------------
// merge partials + build xc (fp16): xch[b] = fp16([emb[tok[b]]; c[b]])
// c[h] = sum_i exp(m_i - M) * c_i[h] / L,  L = sum_i l_i exp(m_i - M)
// ---------------------------------------------------------------------------
__global__ __launch_bounds__(256) void k_merge_xc(const int* __restrict__ tok,
                                                  const float* __restrict__ emb,
                                                  const float* __restrict__ cp,
                                                  const float* __restrict__ ml,
                                                  __half* __restrict__ xch)
{
    __shared__ float ms[NSPA], ls[NSPA];
    const int b = blockIdx.x, tid = threadIdx.x;
    if (tid < NSPA) {
        ms[tid] = ml[(tid * B_ + b) * 2];
        ls[tid] = ml[(tid * B_ + b) * 2 + 1];
    }
    // emb half while waiting
    const int tk = tok[b];
    float4 ev = ((const float4*)(emb + (size_t)tk * E_))[tid];
    {
        __half2 p0 = __floats2half2_rn(ev.x, ev.y);
        __half2 p1 = __floats2half2_rn(ev.z, ev.w);
        uint2 pk;
        pk.x = *reinterpret_cast<uint32_t*>(&p0);
        pk.y = *reinterpret_cast<uint32_t*>(&p1);
        *(uint2*)(xch + (size_t)b * (E_ + H_) + 4 * tid) = pk;
    }
    __syncthreads();
    float M = ms[0];
#pragma unroll
    for (int i = 1; i < NSPA; i++) M = fmaxf(M, ms[i]);
    float sc[NSPA];
    float L = 0.f;
#pragma unroll
    for (int i = 0; i < NSPA; i++) {
        sc[i] = expf(ms[i] - M);
        L += ls[i] * sc[i];
    }
    const float inv = 1.f / L;
    float4 c4 = make_float4(0.f, 0.f, 0.f, 0.f);
#pragma unroll
    for (int i = 0; i < NSPA; i++) {
        float4 v = ((const float4*)(cp + ((size_t)i * B_ + b) * H_))[tid];
        const float s = sc[i] * inv;
        c4.x += s * v.x; c4.y += s * v.y; c4.z += s * v.z; c4.w += s * v.w;
    }
    {
        __half2 p0 = __floats2half2_rn(c4.x, c4.y);
        __half2 p1 = __floats2half2_rn(c4.z, c4.w);
        uint2 pk;
        pk.x = *reinterpret_cast<uint32_t*>(&p0);
        pk.y = *reinterpret_cast<uint32_t*>(&p1);
        *(uint2*)(xch + (size_t)b * (E_ + H_) + E_ + 4 * tid) = pk;
    }
}

// ---------------------------------------------------------------------------
// fp16 HMMA GEMM body. Coalesced W loads, double-buffered smem (1 sync/chunk),
// ldmatrix.x4 fragment loads.
// ---------------------------------------------------------------------------
#define SSTR 40   // smem row stride in halves (80B; 8-row ldmatrix conflict-free)

#define MMA_F16(d, a0, a1, a2, a3, b0, b1)                                    \
    asm volatile("mma.sync.aligned.m16n8k16.row.col.f32.f16.f16.f32 "         \
                 "{%0,%1,%2,%3}, {%4,%5,%6,%7}, {%8,%9}, {%0,%1,%2,%3};"      \
                 : "+f"(d[0]), "+f"(d[1]), "+f"(d[2]), "+f"(d[3])             \
                 : "r"(a0), "r"(a1), "r"(a2), "r"(a3), "r"(b0), "r"(b1))

#define LDSM_X4(r0, r1, r2, r3, addr)                                         \
    asm volatile("ldmatrix.sync.aligned.m8n8.x4.shared.b16 {%0,%1,%2,%3}, [%4];" \
                 : "=r"(r0), "=r"(r1), "=r"(r2), "=r"(r3) : "r"(addr))

__device__ __forceinline__ void gemm_h16_body(
    const __half* __restrict__ A, int lda,
    const float* __restrict__ W,
    const float* __restrict__ bias,
    float* __restrict__ C, size_t ldc,
    int n0, int kbase, int klen)
{
    __shared__ __align__(16) __half Wh[2][128][SSTR];
    __shared__ __align__(16) __half Ash[2][64][SSTR];

    const int tid = threadIdx.x;
    const int wid = tid >> 5, lane = tid & 31;
    const int g = lane >> 2, tg = lane & 3;

    const int wr_base = tid >> 3;
    const int wr_piece = tid & 7;
    const float* wg = W + (size_t)(n0 + wr_base) * lda + kbase + wr_piece * 4;
    const size_t wstep = (size_t)16 * lda;

    const int ar = tid >> 1;
    const int ac = (tid & 1) * 16;
    const __half* ag = A + (size_t)ar * lda + kbase + ac;

    const int lj = lane >> 3;
    const int li = lane & 7;
    const int a_row = (lj & 1) * 8 + li;
    const int a_cs = (lj >> 1) * 8;
    const int b_row = (lj >> 1) * 8 + li;
    const int b_cs = (lj & 1) * 8;

    const uint32_t ash_base = (uint32_t)__cvta_generic_to_shared(&Ash[0][0][0]);
    const uint32_t wh_base = (uint32_t)__cvta_generic_to_shared(&Wh[0][0][0]);

    float acc[4][4][4];
#pragma unroll
    for (int mt = 0; mt < 4; mt++)
#pragma unroll
        for (int nt = 0; nt < 4; nt++)
#pragma unroll
            for (int q = 0; q < 4; q++) acc[mt][nt][q] = 0.f;

    const int nch = klen >> 5;

    float4 wreg[8];
    uint4 areg[2];
#pragma unroll
    for (int p = 0; p < 8; p++) wreg[p] = *(const float4*)(wg + p * wstep);
    areg[0] = ((const uint4*)ag)[0];
    areg[1] = ((const uint4*)ag)[1];

    for (int ch = 0; ch < nch; ch++) {
        const int buf = ch & 1;
#pragma unroll
        for (int p = 0; p < 8; p++) {
            __half2 p0 = __floats2half2_rn(wreg[p].x, wreg[p].y);
            __half2 p1 = __floats2half2_rn(wreg[p].z, wreg[p].w);
            uint2 pk;
            pk.x = *reinterpret_cast<uint32_t*>(&p0);
            pk.y = *reinterpret_cast<uint32_t*>(&p1);
            *(uint2*)&Wh[buf][p * 16 + wr_base][wr_piece * 4] = pk;
        }
        *(uint4*)&Ash[buf][ar][ac] = areg[0];
        *(uint4*)&Ash[buf][ar][ac + 8] = areg[1];
        __syncthreads();
        if (ch + 1 < nch) {
            const float* wg2 = wg + (ch + 1) * 32;
#pragma unroll
            for (int p = 0; p < 8; p++) wreg[p] = *(const float4*)(wg2 + p * wstep);
            const __half* ag2 = ag + (ch + 1) * 32;
            areg[0] = ((const uint4*)ag2)[0];
            areg[1] = ((const uint4*)ag2)[1];
        }
        const uint32_t ab = ash_base + (uint32_t)(buf * 64 * SSTR) * 2;
        const uint32_t wb = wh_base + (uint32_t)((buf * 128 + wid * 32 + b_row) * SSTR) * 2;
#pragma unroll
        for (int ks = 0; ks < 2; ks++) {
            const int k0 = ks * 16;
            uint32_t bf0[4], bf1[4];
            LDSM_X4(bf0[0], bf1[0], bf0[1], bf1[1],
                    wb + (uint32_t)(k0 + b_cs) * 2);
            LDSM_X4(bf0[2], bf1[2], bf0[3], bf1[3],
                    wb + (uint32_t)(16 * SSTR + k0 + b_cs) * 2);
#pragma unroll
            for (int mt = 0; mt < 4; mt++) {
                uint32_t a0, a1, a2, a3;
                LDSM_X4(a0, a1, a2, a3,
                        ab + (uint32_t)((mt * 16 + a_row) * SSTR + k0 + a_cs) * 2);
#pragma unroll
                for (int nt = 0; nt < 4; nt++)
                    MMA_F16(acc[mt][nt], a0, a1, a2, a3, bf0[nt], bf1[nt]);
            }
        }
    }
    __syncthreads();
#pragma unroll
    for (int mt = 0; mt < 4; mt++) {
        const int r0 = mt * 16 + g;
#pragma unroll
        for (int nt = 0; nt < 4; nt++) {
            const int col = n0 + wid * 32 + nt * 8 + 2 * tg;
            float bx = 0.f, by = 0.f;
            if (bias) { float2 bb = *(const float2*)(bias + col); bx = bb.x; by = bb.y; }
            *(float2*)(C + (size_t)r0 * ldc + col) =
                make_float2(acc[mt][nt][0] + bx, acc[mt][nt][1] + by);
            *(float2*)(C + (size_t)(r0 + 8) * ldc + col) =
                make_float2(acc[mt][nt][2] + bx, acc[mt][nt][3] + by);
        }
    }
}

// ---------------------------------------------------------------------------
// GRU GEMMs: grid(24, 12): y<8 -> gi split y (klen 256); y>=8 -> gh split
// ---------------------------------------------------------------------------
__global__ __launch_bounds__(128) void k_gru_h(const __half* __restrict__ xch,
                                               const __half* __restrict__ hlh,
                                               const float* __restrict__ Wih,
                                               const float* __restrict__ Whh,
                                               float* __restrict__ gip,
                                               float* __restrict__ ghp)
{
    const int y = blockIdx.y;
    if (y < 8) {
        gemm_h16_body(xch, E_ + H_, Wih, nullptr,
                      gip + (size_t)y * (64 * 3 * H_), 3 * H_,
                      blockIdx.x * 128, y * 256, 256);
    } else {
        gemm_h16_body(hlh, H_, Whh, nullptr,
                      ghp + (size_t)(y - 8) * (64 * 3 * H_), 3 * H_,
                      blockIdx.x * 128, (y - 8) * 256, 256);
    }
}

// ---------------------------------------------------------------------------
// logits GEMM, persistent work-stealing: grid(296); dynamic n-tile counter.
// ---------------------------------------------------------------------------
__global__ __launch_bounds__(128) void k_logits_h(const __half* __restrict__ Ahalf,
                                                  const float* __restrict__ W,
                                                  const float* __restrict__ bias,
                                                  float* __restrict__ C)
{
    __shared__ int s_tile;
    for (;;) {
        if (threadIdx.x == 0)
            s_tile = atomicAdd(&g_tile_ctr, 1);
        __syncthreads();
        const int tile = s_tile;
        __syncthreads();
        if (tile >= NTILES) return;
        gemm_h16_body(Ahalf, H_, W, bias, C, V_, tile * 128, 0, H_);
    }
}

// ---------------------------------------------------------------------------
// gates: merge partials (gi:8, gh:4), GRU nonlinearity, h_new f32 + fp16.
// Also resets the logits tile counter for the upcoming k_logits_h launch.
// ---------------------------------------------------------------------------
__global__ __launch_bounds__(256) void k_gates(const float* __restrict__ gip,
                                               const float* __restrict__ ghp,
                                               const float* __restrict__ b_ih,
                                               const float* __restrict__ b_hh,
                                               const float* __restrict__ h_last,
                                               float* __restrict__ h_new,
                                               __half* __restrict__ h_half)
{
    if (blockIdx.x == 0 && threadIdx.x == 0)
        g_tile_ctr = 0;
    const int idx = blockIdx.x * blockDim.x + threadIdx.x;
    const int b = idx >> 10;
    const int h = idx & 1023;
    float ir = 0.f, iz = 0.f, in_ = 0.f;
#pragma unroll
    for (int sp = 0; sp < 8; sp++) {
        const float* g = gip + (size_t)(sp * B_ + b) * (3 * H_);
        ir += g[h];
        iz += g[h + H_];
        in_ += g[h + 2 * H_];
    }
    float hr = 0.f, hz = 0.f, hn = 0.f;
#pragma unroll
    for (int sp = 0; sp < 4; sp++) {
        const float* g = ghp + (size_t)(sp * B_ + b) * (3 * H_);
        hr += g[h];
        hz += g[h + H_];
        hn += g[h + 2 * H_];
    }
    ir += b_ih[h];           hr += b_hh[h];
    iz += b_ih[h + H_];      hz += b_hh[h + H_];
    in_ += b_ih[h + 2 * H_]; hn += b_hh[h + 2 * H_];
    const float r = 1.f / (1.f + expf(-(ir + hr)));
    const float z = 1.f / (1.f + expf(-(iz + hz)));
    const float n = tanhf(in_ + r * hn);
    const float hv = (1.f - z) * n + z * h_last[idx];
    h_new[idx] = hv;
    h_half[idx] = __float2half_rn(hv);
}

// ---------------------------------------------------------------------------
extern "C" void kernel_launch(void* const* d_in, const int* in_sizes, int n_in,
                              void* d_out, int out_size)
{
    (void)in_sizes; (void)n_in; (void)out_size;
    const int* dec_input = (const int*)d_in[0];
    const float* dec_hidden = (const float*)d_in[1];
    const float* enc = (const float*)d_in[2];
    const float* emb = (const float*)d_in[3];
    const float* Wa1 = (const float*)d_in[4];
    const float* Wa2 = (const float*)d_in[5];
    const float* W_ih = (const float*)d_in[6];
    const float* W_hh = (const float*)d_in[7];
    const float* b_ih = (const float*)d_in[8];
    const float* b_hh = (const float*)d_in[9];
    const float* W_out = (const float*)d_in[10];
    const float* b_out = (const float*)d_in[11];

    float* out = (float*)d_out;
    float* logits = out;
    float* h_new = out + (size_t)B_ * V_;

    float* scratch = nullptr;
    cudaGetSymbolAddress((void**)&scratch, g_scratch);
    float* hWa1 = scratch + OFF_HWA1;
    __half* xch = (__half*)(scratch + OFF_XCH);
    __half* hlh = (__half*)(scratch + OFF_HLH);
    float* gip = scratch + OFF_GIP;
    float* ghp = scratch + OFF_GHP;
    float* cp = scratch + OFF_CP;
    float* ml = scratch + OFF_ML;
    __half* Ahalf = (__half*)(scratch + OFF_AH);

    // attention (fused single enc pass)
    k_hWa1<<<B_, 256>>>(dec_hidden, Wa1, hWa1, hlh);
    cudaFuncSetAttribute(k_attn, cudaFuncAttributeMaxDynamicSharedMemorySize,
                         ATT_SMEM_FLOATS * 4);
    k_attn<<<dim3(B_, NSPA), 256, ATT_SMEM_FLOATS * 4>>>(enc, Wa1, Wa2, hWa1, cp, ml);
    k_merge_xc<<<B_, 256>>>(dec_input, emb, cp, ml, xch);

    // GRU (fp16 HMMA, fine K-split)
    k_gru_h<<<dim3(3 * H_ / 128, 12), 128>>>(xch, hlh, W_ih, W_hh, gip, ghp);
    k_gates<<<(B_ * H_) / 256, 256>>>(gip, ghp, b_ih, b_hh, dec_hidden, h_new, Ahalf);

    // logits (fp16 HMMA, persistent work-stealing over 250 n-tiles)
    k_logits_h<<<296, 128>>>(Ahalf, W_out, b_out, logits);
}

// round 13
// speedup vs baseline: 1.2072x; 1.2072x over previous
#include <cuda_runtime.h>
#include <cuda_fp16.h>
#include <math.h>
#include <stdint.h>

// Problem dims
#define V_ 32000
#define E_ 1024
#define H_ 1024
#define A_ 10
#define S_ 512
#define B_ 64

#define NSPA 16                // attention S-splits (32 rows each)
#define NTILES (V_ / 128)      // 250 logits n-tiles

// Scratch layout (floats)
#define OFF_HWA1 0             // 640
#define OFF_XCH  1024          // 64*2048 fp16 = 65536 floats
#define OFF_HLH  66560         // 64*1024 fp16 = 32768 floats
#define OFF_GIP  99328         // 8*B*3H = 1572864
#define OFF_GHP  1672192       // 4*B*3H = 786432
#define OFF_CP   2458624       // NSPA*B*H = 1048576
#define OFF_ML   3507200       // NSPA*B*2 = 2048
#define OFF_AH   3509248       // B*H fp16 = 32768 floats
#define SCRATCH_FLOATS 3542016

__device__ float g_scratch[SCRATCH_FLOATS];
__device__ int g_tile_ctr = 0;     // logits work-stealing counter

// ---------------------------------------------------------------------------
// hWa1[b][a] = sum_h h_last[b,h]*Wa1[a,h]; also emit h_last as fp16
// ---------------------------------------------------------------------------
__global__ __launch_bounds__(256) void k_hWa1(const float* __restrict__ h,
                                              const float* __restrict__ Wa1,
                                              float* __restrict__ hWa1,
                                              __half* __restrict__ hlh)
{
    const int b = blockIdx.x;
    const int tid = threadIdx.x;
    float4 hv = ((const float4*)(h + (size_t)b * H_))[tid];
    {
        __half2 p0 = __floats2half2_rn(hv.x, hv.y);
        __half2 p1 = __floats2half2_rn(hv.z, hv.w);
        uint2 pk;
        pk.x = *reinterpret_cast<uint32_t*>(&p0);
        pk.y = *reinterpret_cast<uint32_t*>(&p1);
        *(uint2*)(hlh + (size_t)b * H_ + 4 * tid) = pk;
    }
    float p[A_];
#pragma unroll
    for (int a = 0; a < A_; a++) {
        float4 w = ((const float4*)(Wa1 + (size_t)a * (2 * H_)))[tid];
        p[a] = hv.x * w.x + hv.y * w.y + hv.z * w.z + hv.w * w.w;
    }
    __shared__ float red[8][A_];
    const int lane = tid & 31, wid = tid >> 5;
#pragma unroll
    for (int a = 0; a < A_; a++) {
        float v = p[a];
        v += __shfl_xor_sync(0xffffffffu, v, 16);
        v += __shfl_xor_sync(0xffffffffu, v, 8);
        v += __shfl_xor_sync(0xffffffffu, v, 4);
        v += __shfl_xor_sync(0xffffffffu, v, 2);
        v += __shfl_xor_sync(0xffffffffu, v, 1);
        if (lane == 0) red[wid][a] = v;
    }
    __syncthreads();
    if (tid < A_) {
        float s = 0.f;
#pragma unroll
        for (int w = 0; w < 8; w++) s += red[w][tid];
        hWa1[b * A_ + tid] = s;
    }
}

// ---------------------------------------------------------------------------
// fused attention v2: block = (b, 32-row s-chunk), 256 thr, smem = Wa1 only.
// Phase 1: all 8 warps score 4 rows each, enc straight from gmem.
// Phase 2: block-local softmax numerator context, enc re-read (L2-hot).
// ---------------------------------------------------------------------------
__global__ __launch_bounds__(256) void k_attn(const float* __restrict__ enc,
                                              const float* __restrict__ Wa1,
                                              const float* __restrict__ Wa2,
                                              const float* __restrict__ hWa1,
                                              float* __restrict__ cp,
                                              float* __restrict__ ml)
{
    __shared__ float Wsh[A_ * H_];     // 40KB
    __shared__ float esm[32];
    __shared__ float hWs[A_], wa2s[A_];

    const int b = blockIdx.x, sp = blockIdx.y;
    const int tid = threadIdx.x, wid = tid >> 5, lane = tid & 31;
    const int s0 = sp * 32;

    for (int id = tid; id < A_ * (H_ / 4); id += 256) {
        int a = id >> 8, c4i = id & 255;
        ((float4*)Wsh)[a * 256 + c4i] =
            *(const float4*)(Wa1 + (size_t)a * (2 * H_) + H_ + (c4i << 2));
    }
    if (tid < A_) { hWs[tid] = hWa1[b * A_ + tid]; wa2s[tid] = Wa2[tid]; }
    __syncthreads();

    // score phase: warp w -> rows s0+4w .. s0+4w+3 (same b, consecutive s)
    {
        const float4* r0p = (const float4*)(enc + ((size_t)(s0 + wid * 4 + 0) * B_ + b) * H_);
        const float4* r1p = (const float4*)(enc + ((size_t)(s0 + wid * 4 + 1) * B_ + b) * H_);
        const float4* r2p = (const float4*)(enc + ((size_t)(s0 + wid * 4 + 2) * B_ + b) * H_);
        const float4* r3p = (const float4*)(enc + ((size_t)(s0 + wid * 4 + 3) * B_ + b) * H_);

        float acc0[A_], acc1[A_], acc2[A_], acc3[A_];
#pragma unroll
        for (int a = 0; a < A_; a++) { acc0[a] = 0.f; acc1[a] = 0.f; acc2[a] = 0.f; acc3[a] = 0.f; }

#pragma unroll
        for (int q = 0; q < 8; q++) {
            const int i4 = lane + 32 * q;
            float4 x0 = r0p[i4];
            float4 x1 = r1p[i4];
            float4 x2 = r2p[i4];
            float4 x3 = r3p[i4];
#pragma unroll
            for (int a = 0; a < A_; a++) {
                float4 w = ((const float4*)(Wsh + a * H_))[i4];
                acc0[a] += x0.x * w.x + x0.y * w.y + x0.z * w.z + x0.w * w.w;
                acc1[a] += x1.x * w.x + x1.y * w.y + x1.z * w.z + x1.w * w.w;
                acc2[a] += x2.x * w.x + x2.y * w.y + x2.z * w.z + x2.w * w.w;
                acc3[a] += x3.x * w.x + x3.y * w.y + x3.z * w.z + x3.w * w.w;
            }
        }
#pragma unroll
        for (int a = 0; a < A_; a++) {
            float v;
            v = acc0[a];
            v += __shfl_xor_sync(0xffffffffu, v, 16); v += __shfl_xor_sync(0xffffffffu, v, 8);
            v += __shfl_xor_sync(0xffffffffu, v, 4);  v += __shfl_xor_sync(0xffffffffu, v, 2);
            v += __shfl_xor_sync(0xffffffffu, v, 1);  acc0[a] = v;
            v = acc1[a];
            v += __shfl_xor_sync(0xffffffffu, v, 16); v += __shfl_xor_sync(0xffffffffu, v, 8);
            v += __shfl_xor_sync(0xffffffffu, v, 4);  v += __shfl_xor_sync(0xffffffffu, v, 2);
            v += __shfl_xor_sync(0xffffffffu, v, 1);  acc1[a] = v;
            v = acc2[a];
            v += __shfl_xor_sync(0xffffffffu, v, 16); v += __shfl_xor_sync(0xffffffffu, v, 8);
            v += __shfl_xor_sync(0xffffffffu, v, 4);  v += __shfl_xor_sync(0xffffffffu, v, 2);
            v += __shfl_xor_sync(0xffffffffu, v, 1);  acc2[a] = v;
            v = acc3[a];
            v += __shfl_xor_sync(0xffffffffu, v, 16); v += __shfl_xor_sync(0xffffffffu, v, 8);
            v += __shfl_xor_sync(0xffffffffu, v, 4);  v += __shfl_xor_sync(0xffffffffu, v, 2);
            v += __shfl_xor_sync(0xffffffffu, v, 1);  acc3[a] = v;
        }
        float tsum[A_];
#pragma unroll
        for (int a = 0; a < A_; a++) {
            float t = acc0[a];
            if (lane == 1) t = acc1[a];
            if (lane == 2) t = acc2[a];
            if (lane == 3) t = acc3[a];
            tsum[a] = t;
        }
        if (lane < 4) {
            float ev = 0.f;
#pragma unroll
            for (int a = 0; a < A_; a++)
                ev += wa2s[a] * tanhf(hWs[a] + tsum[a]);
            esm[wid * 4 + lane] = ev;
        }
    }
    __syncthreads();

    // context phase: thread owns float4 h-slot tid; enc rows re-read (L2-hot)
    float mx = esm[0];
#pragma unroll
    for (int r = 1; r < 32; r++) mx = fmaxf(mx, esm[r]);
    float l = 0.f;
    float4 c4 = make_float4(0.f, 0.f, 0.f, 0.f);
#pragma unroll 4
    for (int r = 0; r < 32; r++) {
        const float wr = expf(esm[r] - mx);
        l += wr;
        float4 v = ((const float4*)(enc + ((size_t)(s0 + r) * B_ + b) * H_))[tid];
        c4.x += wr * v.x; c4.y += wr * v.y; c4.z += wr * v.z; c4.w += wr * v.w;
    }
    ((float4*)(cp + ((size_t)sp * B_ + b) * H_))[tid] = c4;
    if (tid == 0) {
        ml[(sp * B_ + b) * 2] = mx;
        ml[(sp * B_ + b) * 2 + 1] = l;
    }
}

// ---------------------------------------------------------------------------
// merge partials + build xc (fp16): xch[b] = fp16([emb[tok[b]]; c[b]])
// c[h] = sum_i exp(m_i - M) * c_i[h] / L,  L = sum_i l_i exp(m_i - M)
// ---------------------------------------------------------------------------
__global__ __launch_bounds__(256) void k_merge_xc(const int* __restrict__ tok,
                                                  const float* __restrict__ emb,
                                                  const float* __restrict__ cp,
                                                  const float* __restrict__ ml,
                                                  __half* __restrict__ xch)
{
    __shared__ float ms[NSPA], ls[NSPA];
    const int b = blockIdx.x, tid = threadIdx.x;
    if (tid < NSPA) {
        ms[tid] = ml[(tid * B_ + b) * 2];
        ls[tid] = ml[(tid * B_ + b) * 2 + 1];
    }
    const int tk = tok[b];
    float4 ev = ((const float4*)(emb + (size_t)tk * E_))[tid];
    {
        __half2 p0 = __floats2half2_rn(ev.x, ev.y);
        __half2 p1 = __floats2half2_rn(ev.z, ev.w);
        uint2 pk;
        pk.x = *reinterpret_cast<uint32_t*>(&p0);
        pk.y = *reinterpret_cast<uint32_t*>(&p1);
        *(uint2*)(xch + (size_t)b * (E_ + H_) + 4 * tid) = pk;
    }
    __syncthreads();
    float M = ms[0];
#pragma unroll
    for (int i = 1; i < NSPA; i++) M = fmaxf(M, ms[i]);
    float sc[NSPA];
    float L = 0.f;
#pragma unroll
    for (int i = 0; i < NSPA; i++) {
        sc[i] = expf(ms[i] - M);
        L += ls[i] * sc[i];
    }
    const float inv = 1.f / L;
    float4 c4 = make_float4(0.f, 0.f, 0.f, 0.f);
#pragma unroll
    for (int i = 0; i < NSPA; i++) {
        float4 v = ((const float4*)(cp + ((size_t)i * B_ + b) * H_))[tid];
        const float s = sc[i] * inv;
        c4.x += s * v.x; c4.y += s * v.y; c4.z += s * v.z; c4.w += s * v.w;
    }
    {
        __half2 p0 = __floats2half2_rn(c4.x, c4.y);
        __half2 p1 = __floats2half2_rn(c4.z, c4.w);
        uint2 pk;
        pk.x = *reinterpret_cast<uint32_t*>(&p0);
        pk.y = *reinterpret_cast<uint32_t*>(&p1);
        *(uint2*)(xch + (size_t)b * (E_ + H_) + E_ + 4 * tid) = pk;
    }
}

// ---------------------------------------------------------------------------
// fp16 HMMA GEMM body. Coalesced W loads, double-buffered smem (1 sync/chunk),
// ldmatrix.x4 fragment loads.
// ---------------------------------------------------------------------------
#define SSTR 40   // smem row stride in halves (80B; 8-row ldmatrix conflict-free)

#define MMA_F16(d, a0, a1, a2, a3, b0, b1)                                    \
    asm volatile("mma.sync.aligned.m16n8k16.row.col.f32.f16.f16.f32 "         \
                 "{%0,%1,%2,%3}, {%4,%5,%6,%7}, {%8,%9}, {%0,%1,%2,%3};"      \
                 : "+f"(d[0]), "+f"(d[1]), "+f"(d[2]), "+f"(d[3])             \
                 : "r"(a0), "r"(a1), "r"(a2), "r"(a3), "r"(b0), "r"(b1))

#define LDSM_X4(r0, r1, r2, r3, addr)                                         \
    asm volatile("ldmatrix.sync.aligned.m8n8.x4.shared.b16 {%0,%1,%2,%3}, [%4];" \
                 : "=r"(r0), "=r"(r1), "=r"(r2), "=r"(r3) : "r"(addr))

__device__ __forceinline__ void gemm_h16_body(
    const __half* __restrict__ A, int lda,
    const float* __restrict__ W,
    const float* __restrict__ bias,
    float* __restrict__ C, size_t ldc,
    int n0, int kbase, int klen)
{
    __shared__ __align__(16) __half Wh[2][128][SSTR];
    __shared__ __align__(16) __half Ash[2][64][SSTR];

    const int tid = threadIdx.x;
    const int wid = tid >> 5, lane = tid & 31;
    const int g = lane >> 2, tg = lane & 3;

    const int wr_base = tid >> 3;
    const int wr_piece = tid & 7;
    const float* wg = W + (size_t)(n0 + wr_base) * lda + kbase + wr_piece * 4;
    const size_t wstep = (size_t)16 * lda;

    const int ar = tid >> 1;
    const int ac = (tid & 1) * 16;
    const __half* ag = A + (size_t)ar * lda + kbase + ac;

    const int lj = lane >> 3;
    const int li = lane & 7;
    const int a_row = (lj & 1) * 8 + li;
    const int a_cs = (lj >> 1) * 8;
    const int b_row = (lj >> 1) * 8 + li;
    const int b_cs = (lj & 1) * 8;

    const uint32_t ash_base = (uint32_t)__cvta_generic_to_shared(&Ash[0][0][0]);
    const uint32_t wh_base = (uint32_t)__cvta_generic_to_shared(&Wh[0][0][0]);

    float acc[4][4][4];
#pragma unroll
    for (int mt = 0; mt < 4; mt++)
#pragma unroll
        for (int nt = 0; nt < 4; nt++)
#pragma unroll
            for (int q = 0; q < 4; q++) acc[mt][nt][q] = 0.f;

    const int nch = klen >> 5;

    float4 wreg[8];
    uint4 areg[2];
#pragma unroll
    for (int p = 0; p < 8; p++) wreg[p] = *(const float4*)(wg + p * wstep);
    areg[0] = ((const uint4*)ag)[0];
    areg[1] = ((const uint4*)ag)[1];

    for (int ch = 0; ch < nch; ch++) {
        const int buf = ch & 1;
#pragma unroll
        for (int p = 0; p < 8; p++) {
            __half2 p0 = __floats2half2_rn(wreg[p].x, wreg[p].y);
            __half2 p1 = __floats2half2_rn(wreg[p].z, wreg[p].w);
            uint2 pk;
            pk.x = *reinterpret_cast<uint32_t*>(&p0);
            pk.y = *reinterpret_cast<uint32_t*>(&p1);
            *(uint2*)&Wh[buf][p * 16 + wr_base][wr_piece * 4] = pk;
        }
        *(uint4*)&Ash[buf][ar][ac] = areg[0];
        *(uint4*)&Ash[buf][ar][ac + 8] = areg[1];
        __syncthreads();
        if (ch + 1 < nch) {
            const float* wg2 = wg + (ch + 1) * 32;
#pragma unroll
            for (int p = 0; p < 8; p++) wreg[p] = *(const float4*)(wg2 + p * wstep);
            const __half* ag2 = ag + (ch + 1) * 32;
            areg[0] = ((const uint4*)ag2)[0];
            areg[1] = ((const uint4*)ag2)[1];
        }
        const uint32_t ab = ash_base + (uint32_t)(buf * 64 * SSTR) * 2;
        const uint32_t wb = wh_base + (uint32_t)((buf * 128 + wid * 32 + b_row) * SSTR) * 2;
#pragma unroll
        for (int ks = 0; ks < 2; ks++) {
            const int k0 = ks * 16;
            uint32_t bf0[4], bf1[4];
            LDSM_X4(bf0[0], bf1[0], bf0[1], bf1[1],
                    wb + (uint32_t)(k0 + b_cs) * 2);
            LDSM_X4(bf0[2], bf1[2], bf0[3], bf1[3],
                    wb + (uint32_t)(16 * SSTR + k0 + b_cs) * 2);
#pragma unroll
            for (int mt = 0; mt < 4; mt++) {
                uint32_t a0, a1, a2, a3;
                LDSM_X4(a0, a1, a2, a3,
                        ab + (uint32_t)((mt * 16 + a_row) * SSTR + k0 + a_cs) * 2);
#pragma unroll
                for (int nt = 0; nt < 4; nt++)
                    MMA_F16(acc[mt][nt], a0, a1, a2, a3, bf0[nt], bf1[nt]);
            }
        }
    }
    __syncthreads();
#pragma unroll
    for (int mt = 0; mt < 4; mt++) {
        const int r0 = mt * 16 + g;
#pragma unroll
        for (int nt = 0; nt < 4; nt++) {
            const int col = n0 + wid * 32 + nt * 8 + 2 * tg;
            float bx = 0.f, by = 0.f;
            if (bias) { float2 bb = *(const float2*)(bias + col); bx = bb.x; by = bb.y; }
            *(float2*)(C + (size_t)r0 * ldc + col) =
                make_float2(acc[mt][nt][0] + bx, acc[mt][nt][1] + by);
            *(float2*)(C + (size_t)(r0 + 8) * ldc + col) =
                make_float2(acc[mt][nt][2] + bx, acc[mt][nt][3] + by);
        }
    }
}

// ---------------------------------------------------------------------------
// GRU GEMMs: grid(24, 12): y<8 -> gi split y (klen 256); y>=8 -> gh split
// ---------------------------------------------------------------------------
__global__ __launch_bounds__(128) void k_gru_h(const __half* __restrict__ xch,
                                               const __half* __restrict__ hlh,
                                               const float* __restrict__ Wih,
                                               const float* __restrict__ Whh,
                                               float* __restrict__ gip,
                                               float* __restrict__ ghp)
{
    const int y = blockIdx.y;
    if (y < 8) {
        gemm_h16_body(xch, E_ + H_, Wih, nullptr,
                      gip + (size_t)y * (64 * 3 * H_), 3 * H_,
                      blockIdx.x * 128, y * 256, 256);
    } else {
        gemm_h16_body(hlh, H_, Whh, nullptr,
                      ghp + (size_t)(y - 8) * (64 * 3 * H_), 3 * H_,
                      blockIdx.x * 128, (y - 8) * 256, 256);
    }
}

// ---------------------------------------------------------------------------
// logits GEMM, persistent work-stealing: grid(296); dynamic n-tile counter.
// ---------------------------------------------------------------------------
__global__ __launch_bounds__(128) void k_logits_h(const __half* __restrict__ Ahalf,
                                                  const float* __restrict__ W,
                                                  const float* __restrict__ bias,
                                                  float* __restrict__ C)
{
    __shared__ int s_tile;
    for (;;) {
        if (threadIdx.x == 0)
            s_tile = atomicAdd(&g_tile_ctr, 1);
        __syncthreads();
        const int tile = s_tile;
        __syncthreads();
        if (tile >= NTILES) return;
        gemm_h16_body(Ahalf, H_, W, bias, C, V_, tile * 128, 0, H_);
    }
}

// ---------------------------------------------------------------------------
// gates: merge partials (gi:8, gh:4), GRU nonlinearity, h_new f32 + fp16.
// Also resets the logits tile counter for the upcoming k_logits_h launch.
// ---------------------------------------------------------------------------
__global__ __launch_bounds__(256) void k_gates(const float* __restrict__ gip,
                                               const float* __restrict__ ghp,
                                               const float* __restrict__ b_ih,
                                               const float* __restrict__ b_hh,
                                               const float* __restrict__ h_last,
                                               float* __restrict__ h_new,
                                               __half* __restrict__ h_half)
{
    if (blockIdx.x == 0 && threadIdx.x == 0)
        g_tile_ctr = 0;
    const int idx = blockIdx.x * blockDim.x + threadIdx.x;
    const int b = idx >> 10;
    const int h = idx & 1023;
    float ir = 0.f, iz = 0.f, in_ = 0.f;
#pragma unroll
    for (int sp = 0; sp < 8; sp++) {
        const float* g = gip + (size_t)(sp * B_ + b) * (3 * H_);
        ir += g[h];
        iz += g[h + H_];
        in_ += g[h + 2 * H_];
    }
    float hr = 0.f, hz = 0.f, hn = 0.f;
#pragma unroll
    for (int sp = 0; sp < 4; sp++) {
        const float* g = ghp + (size_t)(sp * B_ + b) * (3 * H_);
        hr += g[h];
        hz += g[h + H_];
        hn += g[h + 2 * H_];
    }
    ir += b_ih[h];           hr += b_hh[h];
    iz += b_ih[h + H_];      hz += b_hh[h + H_];
    in_ += b_ih[h + 2 * H_]; hn += b_hh[h + 2 * H_];
    const float r = 1.f / (1.f + expf(-(ir + hr)));
    const float z = 1.f / (1.f + expf(-(iz + hz)));
    const float n = tanhf(in_ + r * hn);
    const float hv = (1.f - z) * n + z * h_last[idx];
    h_new[idx] = hv;
    h_half[idx] = __float2half_rn(hv);
}

// ---------------------------------------------------------------------------
extern "C" void kernel_launch(void* const* d_in, const int* in_sizes, int n_in,
                              void* d_out, int out_size)
{
    (void)in_sizes; (void)n_in; (void)out_size;
    const int* dec_input = (const int*)d_in[0];
    const float* dec_hidden = (const float*)d_in[1];
    const float* enc = (const float*)d_in[2];
    const float* emb = (const float*)d_in[3];
    const float* Wa1 = (const float*)d_in[4];
    const float* Wa2 = (const float*)d_in[5];
    const float* W_ih = (const float*)d_in[6];
    const float* W_hh = (const float*)d_in[7];
    const float* b_ih = (const float*)d_in[8];
    const float* b_hh = (const float*)d_in[9];
    const float* W_out = (const float*)d_in[10];
    const float* b_out = (const float*)d_in[11];

    float* out = (float*)d_out;
    float* logits = out;
    float* h_new = out + (size_t)B_ * V_;

    float* scratch = nullptr;
    cudaGetSymbolAddress((void**)&scratch, g_scratch);
    float* hWa1 = scratch + OFF_HWA1;
    __half* xch = (__half*)(scratch + OFF_XCH);
    __half* hlh = (__half*)(scratch + OFF_HLH);
    float* gip = scratch + OFF_GIP;
    float* ghp = scratch + OFF_GHP;
    float* cp = scratch + OFF_CP;
    float* ml = scratch + OFF_ML;
    __half* Ahalf = (__half*)(scratch + OFF_AH);

    // attention (fused, single DRAM enc pass; context re-read is L2-hot)
    k_hWa1<<<B_, 256>>>(dec_hidden, Wa1, hWa1, hlh);
    k_attn<<<dim3(B_, NSPA), 256>>>(enc, Wa1, Wa2, hWa1, cp, ml);
    k_merge_xc<<<B_, 256>>>(dec_input, emb, cp, ml, xch);

    // GRU (fp16 HMMA, fine K-split)
    k_gru_h<<<dim3(3 * H_ / 128, 12), 128>>>(xch, hlh, W_ih, W_hh, gip, ghp);
    k_gates<<<(B_ * H_) / 256, 256>>>(gip, ghp, b_ih, b_hh, dec_hidden, h_new, Ahalf);

    // logits (fp16 HMMA, persistent work-stealing over 250 n-tiles)
    k_logits_h<<<296, 128>>>(Ahalf, W_out, b_out, logits);
}